// round 6
// baseline (speedup 1.0000x reference)
#include <cuda_runtime.h>
#include <cstdint>

#define BB 64
#define TT 512
#define EE 768
#define HH 256
#define VV 3072

__device__ float g_x[TT * BB * HH];   // xWxh laid out [t][b][h]
__device__ float g_h[BB * HH];        // final hidden

// ---------- f32x2 helpers ----------
__device__ __forceinline__ unsigned long long pack2(float lo, float hi) {
    unsigned long long r;
    asm("mov.b64 %0, {%1, %2};" : "=l"(r) : "f"(lo), "f"(hi));
    return r;
}
__device__ __forceinline__ void unpack2(unsigned long long v, float& lo, float& hi) {
    asm("mov.b64 {%0, %1}, %2;" : "=f"(lo), "=f"(hi) : "l"(v));
}
__device__ __forceinline__ unsigned long long fma2(unsigned long long a,
                                                   unsigned long long b,
                                                   unsigned long long c) {
    unsigned long long d;
    asm("fma.rn.f32x2 %0, %1, %2, %3;" : "=l"(d) : "l"(a), "l"(b), "l"(c));
    return d;
}

// =====================================================================
// Phase 1: g_x[t][b][h] = sum_e emb[idx[b][t]][e] * Wxh[e][h]
// M = 32768 (m = b*512 + t), N = 256, K = 768.
// BM=128, BN=128, BK=16; 256 threads; 8x8 microtile f32x2.
// Register-staged double buffer: LDG tile i+2 during compute of tile i,
// STS one tile ahead, 2 smem stages, ONE __syncthreads per tile.
// =====================================================================
__global__ __launch_bounds__(256, 2)
void gemm_emb(const int* __restrict__ idx, const float* __restrict__ emb,
              const float* __restrict__ Wxh) {
    __shared__ __align__(16) float As[2][128][16];
    __shared__ __align__(16) float Bs[2][16][128];

    const int tid = threadIdx.x;
    const int bm = blockIdx.y;
    const int bn = blockIdx.x;

    const int tx = tid & 15;
    const int ty = tid >> 4;

    // A gather mapping: 2 rows/thread, one 16B chunk each
    const int ar = tid >> 2;
    const int ac = (tid & 3) * 4;
    const long r0 = idx[bm * 128 + ar];
    const long r1 = idx[bm * 128 + ar + 64];
    const float* arow0 = emb + r0 * EE + ac;
    const float* arow1 = emb + r1 * EE + ac;

    // B mapping: 2 rows/thread, one 16B chunk each
    const int bkr = tid >> 5;
    const int bc  = (tid & 31) * 4;
    const float* wrow = Wxh + (size_t)bkr * HH + bn * 128 + bc;

    unsigned long long c2[8][4];
#pragma unroll
    for (int i = 0; i < 8; i++)
#pragma unroll
        for (int j = 0; j < 4; j++) c2[i][j] = 0ull;

    const int NT = EE / 16;  // 48 tiles

    float4 ra0, ra1, rb0, rb1;

    // load tile 0 into regs
    ra0 = *reinterpret_cast<const float4*>(arow0);
    ra1 = *reinterpret_cast<const float4*>(arow1);
    rb0 = *reinterpret_cast<const float4*>(wrow);
    rb1 = *reinterpret_cast<const float4*>(wrow + 8 * HH);
    // STS tile 0 -> stage 0
    *reinterpret_cast<float4*>(&As[0][ar][ac])       = ra0;
    *reinterpret_cast<float4*>(&As[0][ar + 64][ac])  = ra1;
    *reinterpret_cast<float4*>(&Bs[0][bkr][bc])      = rb0;
    *reinterpret_cast<float4*>(&Bs[0][bkr + 8][bc])  = rb1;
    // load tile 1 into regs
    ra0 = *reinterpret_cast<const float4*>(arow0 + 16);
    ra1 = *reinterpret_cast<const float4*>(arow1 + 16);
    rb0 = *reinterpret_cast<const float4*>(wrow + (size_t)16 * HH);
    rb1 = *reinterpret_cast<const float4*>(wrow + (size_t)24 * HH);
    __syncthreads();

    const uint32_t bs_base = (uint32_t)__cvta_generic_to_shared(&Bs[0][0][0]);

    for (int i = 0; i < NT; i++) {
        const int s = i & 1;

        if (i + 1 < NT) {
            // STS tile i+1 (in regs) -> stage s^1 (fully read by end of iter i-1)
            const int d = s ^ 1;
            *reinterpret_cast<float4*>(&As[d][ar][ac])      = ra0;
            *reinterpret_cast<float4*>(&As[d][ar + 64][ac]) = ra1;
            *reinterpret_cast<float4*>(&Bs[d][bkr][bc])     = rb0;
            *reinterpret_cast<float4*>(&Bs[d][bkr + 8][bc]) = rb1;
        }
        if (i + 2 < NT) {
            const int kk = (i + 2) * 16;
            ra0 = *reinterpret_cast<const float4*>(arow0 + kk);
            ra1 = *reinterpret_cast<const float4*>(arow1 + kk);
            rb0 = *reinterpret_cast<const float4*>(wrow + (size_t)kk * HH);
            rb1 = *reinterpret_cast<const float4*>(wrow + (size_t)(kk + 8) * HH);
        }

        const uint32_t bs_ld = bs_base + s * 8192 + tx * 32;
#pragma unroll
        for (int k = 0; k < 16; k++) {
            unsigned long long b2[4];
            uint32_t ba = bs_ld + k * 512;
            asm volatile("ld.shared.v2.u64 {%0,%1}, [%2];"
                         : "=l"(b2[0]), "=l"(b2[1]) : "r"(ba));
            asm volatile("ld.shared.v2.u64 {%0,%1}, [%2];"
                         : "=l"(b2[2]), "=l"(b2[3]) : "r"(ba + 16));
#pragma unroll
            for (int ii = 0; ii < 8; ii++) {
                float a = As[s][ty * 8 + ii][k];
                unsigned long long a2 = pack2(a, a);
#pragma unroll
                for (int j = 0; j < 4; j++) c2[ii][j] = fma2(a2, b2[j], c2[ii][j]);
            }
        }
        __syncthreads();
    }

    // Epilogue: m = b*512 + t  ->  g_x[t*B*H + b*H + h]
#pragma unroll
    for (int i = 0; i < 8; i++) {
        int m = bm * 128 + ty * 8 + i;
        int b = m >> 9;
        int t = m & 511;
        float* outp = g_x + (size_t)t * (BB * HH) + b * HH + bn * 128 + tx * 8;
        float4 v0, v1;
        unpack2(c2[i][0], v0.x, v0.y); unpack2(c2[i][1], v0.z, v0.w);
        unpack2(c2[i][2], v1.x, v1.y); unpack2(c2[i][3], v1.z, v1.w);
        *reinterpret_cast<float4*>(outp)     = v0;
        *reinterpret_cast<float4*>(outp + 4) = v1;
    }
}

// =====================================================================
// Phase 2: recurrent scan, cluster of 2 CTAs per batch (rank owns 128 j).
// Thread tid: jl = tid>>2 (0..127), c = tid&3 (quad = 4 i-chunks of 64).
// Quad lanes are adjacent -> partial reduction via 2x shfl_xor (no smem,
// no __syncthreads). ONE barrier.cluster per step (arrive=release,
// wait=acquire: covers local smem stores AND peer DSMEM stores).
// =====================================================================
__global__ __launch_bounds__(512, 1) __cluster_dims__(2, 1, 1)
void rnn_scan(const float* __restrict__ Whh, const float* __restrict__ Bh) {
    __shared__ __align__(16) float hbuf[2][256];

    const int tid = threadIdx.x;
    const int b = blockIdx.x >> 1;
    uint32_t rank;
    asm("mov.u32 %0, %%cluster_ctarank;" : "=r"(rank));
    const uint32_t prank = rank ^ 1u;

    const int jl = tid >> 2;       // 0..127
    const int c  = tid & 3;        // i-chunk
    const int j  = (int)rank * 128 + jl;

    // i-chunk base: c in {0,1} -> this CTA's h rows; {2,3} -> peer's rows
    const int half = c >> 1;
    const int i0 = (half == 0 ? (int)rank : (int)prank) * 128 + (c & 1) * 64;

    // 64 weights (rows i0..i0+63, col j) as 32 f32x2 regs
    unsigned long long w2[32];
#pragma unroll
    for (int p = 0; p < 32; p++) {
        int i = i0 + 2 * p;
        w2[p] = pack2(Whh[i * HH + j], Whh[(i + 1) * HH + j]);
    }
    float bh = 0.f;
    if (c == 0) bh = Bh[j];

    const uint32_t hb_base = (uint32_t)__cvta_generic_to_shared(&hbuf[0][0]);

    // peer address of hbuf[bb][j]
    uint32_t peer_h[2];
#pragma unroll
    for (int bb = 0; bb < 2; bb++) {
        uint32_t lh = hb_base + bb * 1024 + j * 4;
        asm("mapa.shared::cluster.u32 %0, %1, %2;"
            : "=r"(peer_h[bb]) : "r"(lh), "r"(prank));
    }

    if (tid < 256) hbuf[0][tid] = 0.f;
    __syncthreads();
    asm volatile("barrier.cluster.arrive.aligned;" ::: "memory");
    asm volatile("barrier.cluster.wait.aligned;"   ::: "memory");

    const float* xptr = g_x + b * HH + j;
    float xv_cur = 0.f;
    if (c == 0) xv_cur = xptr[0];

    for (int t = 0; t < TT; t++) {
        const int cur = t & 1;
        const int nb  = cur ^ 1;

        float xv = 0.f;
        if (c == 0) {
            xv = xv_cur;
            if (t + 1 < TT) xv_cur = xptr[(size_t)(t + 1) * (BB * HH)];
        }

        // partial = sum_{i in chunk} Whh[i][j] * h[i]
        // stagger start by c to spread shared-memory banks
        const uint32_t ha = hb_base + cur * 1024 + i0 * 4;
        unsigned long long acc0 = 0ull, acc1 = 0ull;
#pragma unroll
        for (int q = 0; q < 8; q++) {
            const int p = (q + c * 2) & 7;
            unsigned long long h0, h1, h2, h3;
            asm volatile("ld.shared.v2.u64 {%0,%1}, [%2];"
                         : "=l"(h0), "=l"(h1) : "r"(ha + p * 32));
            asm volatile("ld.shared.v2.u64 {%0,%1}, [%2];"
                         : "=l"(h2), "=l"(h3) : "r"(ha + p * 32 + 16));
            acc0 = fma2(w2[4 * p + 0], h0, acc0);
            acc1 = fma2(w2[4 * p + 1], h1, acc1);
            acc0 = fma2(w2[4 * p + 2], h2, acc0);
            acc1 = fma2(w2[4 * p + 3], h3, acc1);
        }
        float l0, u0, l1, u1;
        unpack2(acc0, l0, u0); unpack2(acc1, l1, u1);
        float part = (l0 + u0) + (l1 + u1);

        // quad reduction (lanes c=0..3 adjacent)
        part += __shfl_xor_sync(0xFFFFFFFFu, part, 1);
        part += __shfl_xor_sync(0xFFFFFFFFu, part, 2);

        if (c == 0) {
            float s = part + xv + bh;
            float hn = tanhf(s);
            hbuf[nb][j] = hn;                               // local copy
            asm volatile("st.shared::cluster.f32 [%0], %1;" // peer copy
                         :: "r"(peer_h[nb]), "f"(hn) : "memory");
            if (t == TT - 1) g_h[b * HH + j] = hn;
        }

        // single cluster barrier: releases local+remote stores, syncs CTA too
        asm volatile("barrier.cluster.arrive.aligned;" ::: "memory");
        asm volatile("barrier.cluster.wait.aligned;"   ::: "memory");
    }
    // last iteration's barrier already fenced all in-flight remote stores
}

// =====================================================================
// Phase 3: out[b][v] = g_h[b] @ Wy + By.  2 batches per CTA.
// =====================================================================
__global__ __launch_bounds__(256)
void out_proj(const float* __restrict__ Wy, const float* __restrict__ By,
              float* __restrict__ out, int out_size) {
    if (blockIdx.x == 384) {
        if (out_size >= BB * VV + BB * HH) {
            for (int i = threadIdx.x; i < BB * HH; i += 256)
                out[BB * VV + i] = g_h[i];
        }
        return;
    }
    __shared__ float hs[2][HH];
    const int b0 = (blockIdx.x / 12) * 2;
    const int vt = blockIdx.x % 12;
    const int v  = vt * 256 + threadIdx.x;

    hs[0][threadIdx.x] = g_h[b0 * HH + threadIdx.x];
    hs[1][threadIdx.x] = g_h[(b0 + 1) * HH + threadIdx.x];
    __syncthreads();

    float acc0 = 0.f, acc1 = 0.f;
#pragma unroll 8
    for (int h = 0; h < HH; h++) {
        float w = Wy[(size_t)h * VV + v];
        acc0 += hs[0][h] * w;
        acc1 += hs[1][h] * w;
    }
    float by = By[v];
    out[(size_t)b0 * VV + v]       = acc0 + by;
    out[(size_t)(b0 + 1) * VV + v] = acc1 + by;
}

// =====================================================================
extern "C" void kernel_launch(void* const* d_in, const int* in_sizes, int n_in,
                              void* d_out, int out_size) {
    const int*   idx = (const int*)d_in[0];
    const float* emb = (const float*)d_in[1];
    const float* Wxh = (const float*)d_in[2];
    const float* Whh = (const float*)d_in[3];
    const float* Wy  = (const float*)d_in[4];
    const float* By  = (const float*)d_in[5];
    const float* Bh  = (const float*)d_in[6];
    float* out = (float*)d_out;

    gemm_emb<<<dim3(2, 256), 256>>>(idx, emb, Wxh);
    rnn_scan<<<128, 512>>>(Whh, Bh);
    out_proj<<<385, 256>>>(Wy, By, out, out_size);
}

// round 7
// speedup vs baseline: 2.5390x; 2.5390x over previous
#include <cuda_runtime.h>
#include <cstdint>

#define BB 64
#define TT 512
#define EE 768
#define HH 256
#define VV 3072

__device__ float g_x[TT * BB * HH];   // xWxh laid out [t][b][h]
__device__ float g_h[BB * HH];        // final hidden

// ---------- f32x2 helpers ----------
__device__ __forceinline__ unsigned long long pack2(float lo, float hi) {
    unsigned long long r;
    asm("mov.b64 %0, {%1, %2};" : "=l"(r) : "f"(lo), "f"(hi));
    return r;
}
__device__ __forceinline__ void unpack2(unsigned long long v, float& lo, float& hi) {
    asm("mov.b64 {%0, %1}, %2;" : "=f"(lo), "=f"(hi) : "l"(v));
}
__device__ __forceinline__ unsigned long long fma2(unsigned long long a,
                                                   unsigned long long b,
                                                   unsigned long long c) {
    unsigned long long d;
    asm("fma.rn.f32x2 %0, %1, %2, %3;" : "=l"(d) : "l"(a), "l"(b), "l"(c));
    return d;
}
__device__ __forceinline__ void cp16(uint32_t dst, const void* src) {
    asm volatile("cp.async.cg.shared.global [%0], [%1], 16;" :: "r"(dst), "l"(src));
}

// =====================================================================
// Phase 1: g_x[t][b][h] = sum_e emb[idx[b][t]][e] * Wxh[e][h]
// M=32768, N=256, K=768. BM=128, BN=128, BK=16; 256 threads; 8x8 f32x2.
// Static 2-stage cp.async pipeline, one __syncthreads per tile.
// A-column values hoisted as float4 (v4 LDS) per 4-k block.
// =====================================================================
__global__ __launch_bounds__(256, 2)
void gemm_emb(const int* __restrict__ idx, const float* __restrict__ emb,
              const float* __restrict__ Wxh) {
    __shared__ __align__(16) float As[2][128][16];
    __shared__ __align__(16) float Bs[2][16][128];

    const int tid = threadIdx.x;
    const int bm = blockIdx.y;
    const int bn = blockIdx.x;

    const int tx = tid & 15;
    const int ty = tid >> 4;

    // A gather: each thread = 1 row (ar), 8 k-cols starting at acol
    const int ar   = tid >> 1;
    const int acol = (tid & 1) * 8;
    const long rr = idx[bm * 128 + ar];
    const float* asrc = emb + rr * EE + acol;

    // B: each thread = 1 k-row (br), 8 n-cols starting at bcol
    const int br   = tid >> 4;
    const int bcol = (tid & 15) * 8;
    const float* bsrc = Wxh + (size_t)br * HH + bn * 128 + bcol;

    const uint32_t as_base = (uint32_t)__cvta_generic_to_shared(&As[0][0][0]);
    const uint32_t bs_base = (uint32_t)__cvta_generic_to_shared(&Bs[0][0][0]);
    const uint32_t aD = as_base + (ar * 16 + acol) * 4;
    const uint32_t bD = bs_base + (br * 128 + bcol) * 4;

    unsigned long long c2[8][4];
#pragma unroll
    for (int i = 0; i < 8; i++)
#pragma unroll
        for (int j = 0; j < 4; j++) c2[i][j] = 0ull;

    const int NT = EE / 16;  // 48 (even)

    // issue tile n into stage s
#define ISSUE_TILE(n, s)                                                     \
    do {                                                                     \
        const float* a_ = asrc + (n) * 16;                                   \
        const float* b_ = bsrc + (size_t)(n) * 16 * HH;                      \
        cp16(aD + (s) * 8192, a_);      cp16(aD + (s) * 8192 + 16, a_ + 4);  \
        cp16(bD + (s) * 8192, b_);      cp16(bD + (s) * 8192 + 16, b_ + 4);  \
        asm volatile("cp.async.commit_group;");                              \
    } while (0)

#define COMPUTE_STEP(i, s)                                                   \
    do {                                                                     \
        asm volatile("cp.async.wait_group 0;");                              \
        __syncthreads();                                                     \
        if ((i) + 1 < NT) ISSUE_TILE((i) + 1, (s) ^ 1);                      \
        const uint32_t bld = bs_base + (s) * 8192 + tx * 32;                 \
        const uint32_t ald = as_base + (s) * 8192 + ty * 8 * 64;             \
        _Pragma("unroll")                                                    \
        for (int kq = 0; kq < 4; kq++) {                                     \
            float4 av[8];                                                    \
            _Pragma("unroll")                                                \
            for (int ii = 0; ii < 8; ii++) {                                 \
                uint32_t aa = ald + ii * 64 + kq * 16;                       \
                asm volatile("ld.shared.v4.f32 {%0,%1,%2,%3}, [%4];"         \
                    : "=f"(av[ii].x), "=f"(av[ii].y),                        \
                      "=f"(av[ii].z), "=f"(av[ii].w) : "r"(aa));             \
            }                                                                \
            _Pragma("unroll")                                                \
            for (int m = 0; m < 4; m++) {                                    \
                const int k = kq * 4 + m;                                    \
                unsigned long long b2[4];                                    \
                uint32_t ba = bld + k * 512;                                 \
                asm volatile("ld.shared.v2.u64 {%0,%1}, [%2];"               \
                             : "=l"(b2[0]), "=l"(b2[1]) : "r"(ba));          \
                asm volatile("ld.shared.v2.u64 {%0,%1}, [%2];"               \
                             : "=l"(b2[2]), "=l"(b2[3]) : "r"(ba + 16));     \
                _Pragma("unroll")                                            \
                for (int ii = 0; ii < 8; ii++) {                             \
                    float a_ = (m == 0) ? av[ii].x : (m == 1) ? av[ii].y     \
                             : (m == 2) ? av[ii].z : av[ii].w;               \
                    unsigned long long a2 = pack2(a_, a_);                   \
                    _Pragma("unroll")                                        \
                    for (int j = 0; j < 4; j++)                              \
                        c2[ii][j] = fma2(a2, b2[j], c2[ii][j]);              \
                }                                                            \
            }                                                                \
        }                                                                    \
    } while (0)

    ISSUE_TILE(0, 0);
    for (int i = 0; i < NT; i += 2) {
        COMPUTE_STEP(i, 0);
        COMPUTE_STEP(i + 1, 1);
    }
#undef ISSUE_TILE
#undef COMPUTE_STEP

    // Epilogue: m = b*512 + t  ->  g_x[t*B*H + b*H + h]
#pragma unroll
    for (int i = 0; i < 8; i++) {
        int m = bm * 128 + ty * 8 + i;
        int b = m >> 9;
        int t = m & 511;
        float* outp = g_x + (size_t)t * (BB * HH) + b * HH + bn * 128 + tx * 8;
        float4 v0, v1;
        unpack2(c2[i][0], v0.x, v0.y); unpack2(c2[i][1], v0.z, v0.w);
        unpack2(c2[i][2], v1.x, v1.y); unpack2(c2[i][3], v1.z, v1.w);
        *reinterpret_cast<float4*>(outp)     = v0;
        *reinterpret_cast<float4*>(outp + 4) = v1;
    }
}

// =====================================================================
// Phase 2: recurrent scan. Cluster of 2 CTAs per batch, 1024 thr/CTA.
// Grid = 128 CTAs -> ONE wave on 148 SMs.
// Layout: jl = tid&127, c = tid>>7 (8 i-chunks of 32). All w2 indexing
// is compile-time static (R6 lesson: dynamic indexing spills to local).
// Per step: partials -> psum smem -> __syncthreads -> c0 combines,
// tanh, local + peer DSMEM store -> ONE barrier.cluster (proven R2
// semantics: arrive=release / wait=acquire covers all stores).
// =====================================================================
__global__ __launch_bounds__(1024, 1) __cluster_dims__(2, 1, 1)
void rnn_scan(const float* __restrict__ Whh, const float* __restrict__ Bh) {
    __shared__ __align__(16) float hbuf[2][256];
    __shared__ float psum[7][128];

    const int tid = threadIdx.x;
    const int b = blockIdx.x >> 1;
    uint32_t rank;
    asm("mov.u32 %0, %%cluster_ctarank;" : "=r"(rank));
    const uint32_t prank = rank ^ 1u;

    const int jl = tid & 127;
    const int c  = tid >> 7;            // 0..7
    const int j  = (int)rank * 128 + jl;
    const int i0 = c * 32;

    // 32 weights (rows i0..i0+31, col j) as 16 f32x2 regs
    unsigned long long w2[16];
#pragma unroll
    for (int p = 0; p < 16; p++) {
        int i = i0 + 2 * p;
        w2[p] = pack2(Whh[i * HH + j], Whh[(i + 1) * HH + j]);
    }
    float bh = 0.f;
    if (c == 0) bh = Bh[j];

    const uint32_t hb_base = (uint32_t)__cvta_generic_to_shared(&hbuf[0][0]);

    uint32_t peer_h[2];
#pragma unroll
    for (int bb = 0; bb < 2; bb++) {
        uint32_t lh = hb_base + bb * 1024 + j * 4;
        asm("mapa.shared::cluster.u32 %0, %1, %2;"
            : "=r"(peer_h[bb]) : "r"(lh), "r"(prank));
    }

    if (tid < 256) hbuf[0][tid] = 0.f;
    __syncthreads();
    asm volatile("barrier.cluster.arrive.aligned;" ::: "memory");
    asm volatile("barrier.cluster.wait.aligned;"   ::: "memory");

    const float* xptr = g_x + b * HH + j;
    float xv_cur = 0.f;
    if (c == 0) xv_cur = xptr[0];

    for (int t = 0; t < TT; t++) {
        const int cur = t & 1;
        const int nb  = cur ^ 1;

        float xv = 0.f;
        if (c == 0) {
            xv = xv_cur;
            if (t + 1 < TT) xv_cur = xptr[(size_t)(t + 1) * (BB * HH)];
        }

        // partial = sum_{i in chunk of 32} Whh[i][j] * h[i]
        const uint32_t ha = hb_base + cur * 1024 + i0 * 4;
        unsigned long long acc0 = 0ull, acc1 = 0ull;
#pragma unroll
        for (int p = 0; p < 4; p++) {
            unsigned long long h0, h1, h2, h3;
            asm volatile("ld.shared.v2.u64 {%0,%1}, [%2];"
                         : "=l"(h0), "=l"(h1) : "r"(ha + p * 32));
            asm volatile("ld.shared.v2.u64 {%0,%1}, [%2];"
                         : "=l"(h2), "=l"(h3) : "r"(ha + p * 32 + 16));
            acc0 = fma2(w2[4 * p + 0], h0, acc0);
            acc1 = fma2(w2[4 * p + 1], h1, acc1);
            acc0 = fma2(w2[4 * p + 2], h2, acc0);
            acc1 = fma2(w2[4 * p + 3], h3, acc1);
        }
        float l0, u0, l1, u1;
        unpack2(acc0, l0, u0); unpack2(acc1, l1, u1);
        float part = (l0 + u0) + (l1 + u1);

        if (c > 0) psum[c - 1][jl] = part;
        __syncthreads();

        if (c == 0) {
            float s = part + psum[0][jl] + psum[1][jl] + psum[2][jl]
                           + psum[3][jl] + psum[4][jl] + psum[5][jl]
                           + psum[6][jl] + xv + bh;
            float hn = tanhf(s);
            hbuf[nb][j] = hn;                               // local copy
            asm volatile("st.shared::cluster.f32 [%0], %1;" // peer copy
                         :: "r"(peer_h[nb]), "f"(hn) : "memory");
            if (t == TT - 1) g_h[b * HH + j] = hn;
        }

        asm volatile("barrier.cluster.arrive.aligned;" ::: "memory");
        asm volatile("barrier.cluster.wait.aligned;"   ::: "memory");
    }
    // final iteration's cluster barrier fences all in-flight remote stores
}

// =====================================================================
// Phase 3: out[b][v] = g_h[b] @ Wy + By.  2 batches per CTA.
// =====================================================================
__global__ __launch_bounds__(256)
void out_proj(const float* __restrict__ Wy, const float* __restrict__ By,
              float* __restrict__ out, int out_size) {
    if (blockIdx.x == 384) {
        if (out_size >= BB * VV + BB * HH) {
            for (int i = threadIdx.x; i < BB * HH; i += 256)
                out[BB * VV + i] = g_h[i];
        }
        return;
    }
    __shared__ float hs[2][HH];
    const int b0 = (blockIdx.x / 12) * 2;
    const int vt = blockIdx.x % 12;
    const int v  = vt * 256 + threadIdx.x;

    hs[0][threadIdx.x] = g_h[b0 * HH + threadIdx.x];
    hs[1][threadIdx.x] = g_h[(b0 + 1) * HH + threadIdx.x];
    __syncthreads();

    float acc0 = 0.f, acc1 = 0.f;
#pragma unroll 8
    for (int h = 0; h < HH; h++) {
        float w = Wy[(size_t)h * VV + v];
        acc0 += hs[0][h] * w;
        acc1 += hs[1][h] * w;
    }
    float by = By[v];
    out[(size_t)b0 * VV + v]       = acc0 + by;
    out[(size_t)(b0 + 1) * VV + v] = acc1 + by;
}

// =====================================================================
extern "C" void kernel_launch(void* const* d_in, const int* in_sizes, int n_in,
                              void* d_out, int out_size) {
    const int*   idx = (const int*)d_in[0];
    const float* emb = (const float*)d_in[1];
    const float* Wxh = (const float*)d_in[2];
    const float* Whh = (const float*)d_in[3];
    const float* Wy  = (const float*)d_in[4];
    const float* By  = (const float*)d_in[5];
    const float* Bh  = (const float*)d_in[6];
    float* out = (float*)d_out;

    gemm_emb<<<dim3(2, 256), 256>>>(idx, emb, Wxh);
    rnn_scan<<<128, 1024>>>(Whh, Bh);
    out_proj<<<385, 256>>>(Wy, By, out, out_size);
}